// round 1
// baseline (speedup 1.0000x reference)
#include <cuda_runtime.h>
#include <math.h>

#define HID    4096
#define NHEADS 32
#define HDIM   128
#define BATCH  2
#define SEQ    1024
#define TOKENS 2048
#define H3     12288

// ---------------- scratch (device globals; no runtime allocation) ----------------
__device__ __align__(16) float g_norm[(size_t)TOKENS * HID];                    //  33.5 MB
__device__ __align__(16) float g_qkv[(size_t)TOKENS * H3];                      // 100.7 MB
__device__ __align__(16) float g_scores[(size_t)BATCH * NHEADS * SEQ * SEQ];    // 268.4 MB
__device__ __align__(16) float g_ctx[(size_t)TOKENS * HID];                     //  33.5 MB

// ---------------- LayerNorm: one block per token ----------------
__global__ __launch_bounds__(256) void ln_kernel(
    const float* __restrict__ x, const float* __restrict__ w,
    const float* __restrict__ bvec, float* __restrict__ out)
{
    int row = blockIdx.x;
    int tid = threadIdx.x;
    const float* xr = x + (size_t)row * HID;
    float4 v[4];
    float sum = 0.f, ss = 0.f;
#pragma unroll
    for (int i = 0; i < 4; i++) {
        v[i] = *(const float4*)(xr + (i * 256 + tid) * 4);
        sum += v[i].x + v[i].y + v[i].z + v[i].w;
        ss  += v[i].x * v[i].x + v[i].y * v[i].y + v[i].z * v[i].z + v[i].w * v[i].w;
    }
#pragma unroll
    for (int off = 16; off > 0; off >>= 1) {
        sum += __shfl_xor_sync(0xffffffffu, sum, off);
        ss  += __shfl_xor_sync(0xffffffffu, ss,  off);
    }
    __shared__ float r0[8], r1[8];
    __shared__ float s_mu, s_rstd;
    int wid = tid >> 5, lane = tid & 31;
    if (lane == 0) { r0[wid] = sum; r1[wid] = ss; }
    __syncthreads();
    if (tid == 0) {
        float s = 0.f, q = 0.f;
        for (int i = 0; i < 8; i++) { s += r0[i]; q += r1[i]; }
        float mu  = s * (1.f / HID);
        float var = q * (1.f / HID) - mu * mu;
        s_mu = mu; s_rstd = rsqrtf(var + 1e-5f);
    }
    __syncthreads();
    float mu = s_mu, rstd = s_rstd;
    float* outr = out + (size_t)row * HID;
#pragma unroll
    for (int i = 0; i < 4; i++) {
        int c = (i * 256 + tid) * 4;
        float4 wv = *(const float4*)(w + c);
        float4 bv = *(const float4*)(bvec + c);
        float4 o;
        o.x = (v[i].x - mu) * rstd * wv.x + bv.x;
        o.y = (v[i].y - mu) * rstd * wv.y + bv.y;
        o.z = (v[i].z - mu) * rstd * wv.z + bv.z;
        o.w = (v[i].w - mu) * rstd * wv.w + bv.w;
        *(float4*)(outr + c) = o;
    }
}

// ---------------- generic batched SGEMM ----------------
// C[m,n] = alpha * sum_k A[m,k] * B(k,n)  (+ bias[n])
// TRANS_B=false: B is [K,N] row-major.  TRANS_B=true: B is [N,K] row-major (B^T GEMM).
// Batch z: sub-offsets offX = (z>>5)*sX1 + (z&31)*sX2   (b = z/NH, h = z%NH).
// Tiles: 128x128x8, 256 threads, 8x8 per thread. All dims assumed tile-divisible.
#define BM 128
#define BN 128
#define BK 8
#define TM 8
#define TN 8

template<bool TRANS_B, bool CAUSAL, bool HAS_BIAS>
__global__ __launch_bounds__(256) void sgemm_k(
    const float* __restrict__ Ab, const float* __restrict__ Bb,
    const float* __restrict__ bias, float* __restrict__ Cb,
    int K, int lda, int ldb, int ldc,
    long long sA1, long long sA2,
    long long sB1, long long sB2,
    long long sC1, long long sC2,
    float alpha)
{
    int bn = blockIdx.x, bm = blockIdx.y;
    if (CAUSAL && bn > bm) return;   // BM==BN: block fully above the diagonal
    int z = blockIdx.z;
    const float* A = Ab + (long long)(z >> 5) * sA1 + (long long)(z & 31) * sA2;
    const float* B = Bb + (long long)(z >> 5) * sB1 + (long long)(z & 31) * sB2;
    float*       C = Cb + (long long)(z >> 5) * sC1 + (long long)(z & 31) * sC2;

    __shared__ float As[BK][BM];
    __shared__ float Bs[BK][BN];

    int tid = threadIdx.x;
    int tx = tid & 15;    // output col tile
    int ty = tid >> 4;    // output row tile

    // A loader: 128 rows x 8 k, 4 contiguous k per thread
    int arow = tid >> 1;
    int acol = (tid & 1) * 4;
    const float* Aptr = A + (long long)(bm * BM + arow) * lda + acol;

    const float* Bptr;
    int brow = 0, bcol = 0;
    if (TRANS_B) {
        Bptr = B + (long long)(bn * BN + arow) * ldb + acol;
    } else {
        brow = tid >> 5;          // 0..7 (k)
        bcol = (tid & 31) * 4;    // 0..124 (n)
        Bptr = B + (long long)brow * ldb + bn * BN + bcol;
    }

    float acc[TM][TN] = {};

    for (int k0 = 0; k0 < K; k0 += BK) {
        float4 av = *(const float4*)(Aptr);
        Aptr += BK;
        As[acol + 0][arow] = av.x;
        As[acol + 1][arow] = av.y;
        As[acol + 2][arow] = av.z;
        As[acol + 3][arow] = av.w;
        if (TRANS_B) {
            float4 bv = *(const float4*)(Bptr);
            Bptr += BK;
            Bs[acol + 0][arow] = bv.x;
            Bs[acol + 1][arow] = bv.y;
            Bs[acol + 2][arow] = bv.z;
            Bs[acol + 3][arow] = bv.w;
        } else {
            float4 bv = *(const float4*)(Bptr);
            Bptr += (long long)BK * ldb;
            *(float4*)&Bs[brow][bcol] = bv;
        }
        __syncthreads();

#pragma unroll
        for (int kk = 0; kk < BK; kk++) {
            float4 a0 = *(const float4*)&As[kk][ty * TM];
            float4 a1 = *(const float4*)&As[kk][ty * TM + 4];
            float4 b0 = *(const float4*)&Bs[kk][tx * TN];
            float4 b1 = *(const float4*)&Bs[kk][tx * TN + 4];
            float af[TM] = {a0.x, a0.y, a0.z, a0.w, a1.x, a1.y, a1.z, a1.w};
            float bf[TN] = {b0.x, b0.y, b0.z, b0.w, b1.x, b1.y, b1.z, b1.w};
#pragma unroll
            for (int i = 0; i < TM; i++)
#pragma unroll
                for (int j = 0; j < TN; j++)
                    acc[i][j] += af[i] * bf[j];
        }
        __syncthreads();
    }

#pragma unroll
    for (int i = 0; i < TM; i++) {
        long long crow = (long long)(bm * BM + ty * TM + i) * ldc;
#pragma unroll
        for (int j = 0; j < TN; j += 4) {
            int col = bn * BN + tx * TN + j;
            float4 o;
            o.x = acc[i][j + 0] * alpha;
            o.y = acc[i][j + 1] * alpha;
            o.z = acc[i][j + 2] * alpha;
            o.w = acc[i][j + 3] * alpha;
            if (HAS_BIAS) {
                float4 bb = *(const float4*)(bias + col);
                o.x += bb.x; o.y += bb.y; o.z += bb.z; o.w += bb.w;
            }
            *(float4*)(C + crow + col) = o;
        }
    }
}

// ---------------- causal softmax over score rows ----------------
// grid: (SEQ, NHEADS, BATCH); block 256; row length SEQ=1024 (4 per thread)
__global__ __launch_bounds__(256) void softmax_kernel(
    float* __restrict__ scores, const float* __restrict__ mask)
{
    int q = blockIdx.x, h = blockIdx.y, b = blockIdx.z;
    float* row = scores + (((long long)(b * NHEADS + h) * SEQ + q) * SEQ);
    int tid = threadIdx.x;
    int c0 = tid * 4;

    float4 v  = *(const float4*)(row + c0);
    float4 mk = *(const float4*)(mask + b * SEQ + c0);
    float vals[4] = {v.x + mk.x, v.y + mk.y, v.z + mk.z, v.w + mk.w};
#pragma unroll
    for (int j = 0; j < 4; j++)
        if (c0 + j > q) vals[j] += -10000.0f;

    float m = fmaxf(fmaxf(vals[0], vals[1]), fmaxf(vals[2], vals[3]));
#pragma unroll
    for (int off = 16; off > 0; off >>= 1)
        m = fmaxf(m, __shfl_xor_sync(0xffffffffu, m, off));

    __shared__ float rmax[8], rsum[8];
    __shared__ float s_max, s_inv;
    int wid = tid >> 5, lane = tid & 31;
    if (lane == 0) rmax[wid] = m;
    __syncthreads();
    if (tid == 0) {
        float t = rmax[0];
        for (int i = 1; i < 8; i++) t = fmaxf(t, rmax[i]);
        s_max = t;
    }
    __syncthreads();
    float rowmax = s_max;

    float e[4], sum = 0.f;
#pragma unroll
    for (int j = 0; j < 4; j++) { e[j] = __expf(vals[j] - rowmax); sum += e[j]; }
#pragma unroll
    for (int off = 16; off > 0; off >>= 1)
        sum += __shfl_xor_sync(0xffffffffu, sum, off);
    if (lane == 0) rsum[wid] = sum;
    __syncthreads();
    if (tid == 0) {
        float t = 0.f;
        for (int i = 0; i < 8; i++) t += rsum[i];
        s_inv = 1.f / t;
    }
    __syncthreads();
    float inv = s_inv;

    float4 o;
    o.x = e[0] * inv; o.y = e[1] * inv; o.z = e[2] * inv; o.w = e[3] * inv;
    *(float4*)(row + c0) = o;
}

// ---------------- launch ----------------
extern "C" void kernel_launch(void* const* d_in, const int* in_sizes, int n_in,
                              void* d_out, int out_size)
{
    const float* x       = (const float*)d_in[0];
    const float* mask    = (const float*)d_in[1];
    const float* norm_w  = (const float*)d_in[2];
    const float* norm_b  = (const float*)d_in[3];
    const float* qkv_w   = (const float*)d_in[4];
    const float* qkv_b   = (const float*)d_in[5];
    const float* attn_ow = (const float*)d_in[6];
    float* out = (float*)d_out;

    float *p_norm, *p_qkv, *p_scores, *p_ctx;
    cudaGetSymbolAddress((void**)&p_norm,   g_norm);
    cudaGetSymbolAddress((void**)&p_qkv,    g_qkv);
    cudaGetSymbolAddress((void**)&p_scores, g_scores);
    cudaGetSymbolAddress((void**)&p_ctx,    g_ctx);

    const float inv_sqrt_hd = 0.08838834764831845f;  // 1/sqrt(128)

    // 1) LayerNorm
    ln_kernel<<<TOKENS, 256>>>(x, norm_w, norm_b, p_norm);

    // 2) QKV GEMM + bias: [2048,4096] @ [4096,12288]
    sgemm_k<false, false, true><<<dim3(H3 / BN, TOKENS / BM, 1), 256>>>(
        p_norm, qkv_w, qkv_b, p_qkv,
        HID, HID, H3, H3,
        0, 0, 0, 0, 0, 0, 1.0f);

    // 3) scores = Q @ K^T * 1/sqrt(hd), batched over (b,h), causal block skip
    sgemm_k<true, true, false><<<dim3(SEQ / BN, SEQ / BM, BATCH * NHEADS), 256>>>(
        p_qkv, p_qkv + HID, nullptr, p_scores,
        HDIM, H3, H3, SEQ,
        (long long)SEQ * H3, HDIM,
        (long long)SEQ * H3, HDIM,
        (long long)NHEADS * SEQ * SEQ, (long long)SEQ * SEQ,
        inv_sqrt_hd);

    // 4) causal softmax (+ additive input mask)
    softmax_kernel<<<dim3(SEQ, NHEADS, BATCH), 256>>>(p_scores, mask);

    // 5) ctx = P @ V, batched, written directly into [b, s, h*hd + d] layout
    sgemm_k<false, false, false><<<dim3(HDIM / BN, SEQ / BM, BATCH * NHEADS), 256>>>(
        p_scores, p_qkv + 2 * HID, nullptr, p_ctx,
        SEQ, SEQ, H3, HID,
        (long long)NHEADS * SEQ * SEQ, (long long)SEQ * SEQ,
        (long long)SEQ * H3, HDIM,
        (long long)SEQ * HID, HDIM,
        1.0f);

    // 6) out = ctx @ attn_ow : [2048,4096] @ [4096,4096]
    sgemm_k<false, false, false><<<dim3(HID / BN, TOKENS / BM, 1), 256>>>(
        p_ctx, attn_ow, nullptr, out,
        HID, HID, HID, HID,
        0, 0, 0, 0, 0, 0, 1.0f);
}

// round 3
// speedup vs baseline: 2.3872x; 2.3872x over previous
#include <cuda_runtime.h>
#include <cuda_bf16.h>
#include <cstdint>
#include <math.h>

#define HID    4096
#define NHEADS 32
#define HDIM   128
#define BATCH  2
#define SEQ    1024
#define TOKENS 2048
#define H3     12288

// ================= scratch (device globals) =================
__device__ __align__(16) __nv_bfloat16 g_a_hi[(size_t)TOKENS * HID];
__device__ __align__(16) __nv_bfloat16 g_a_lo[(size_t)TOKENS * HID];
__device__ __align__(16) __nv_bfloat16 g_wq_hi[(size_t)H3 * HID];     // qkv_w^T [N,K]
__device__ __align__(16) __nv_bfloat16 g_wq_lo[(size_t)H3 * HID];
__device__ __align__(16) __nv_bfloat16 g_wo_hi[(size_t)HID * HID];    // attn_ow^T [N,K]
__device__ __align__(16) __nv_bfloat16 g_wo_lo[(size_t)HID * HID];
__device__ __align__(16) float g_qkv[(size_t)TOKENS * H3];
__device__ __align__(16) float g_scores[(size_t)BATCH * NHEADS * SEQ * SEQ];
__device__ __align__(16) float g_ctx[(size_t)TOKENS * HID];
__device__ __align__(16) __nv_bfloat16 g_c_hi[(size_t)TOKENS * HID];
__device__ __align__(16) __nv_bfloat16 g_c_lo[(size_t)TOKENS * HID];

// ================= helpers =================
__device__ __forceinline__ uint32_t smem_u32(const void* p) {
    uint32_t a;
    asm("{ .reg .u64 t; cvta.to.shared.u64 t, %1; cvt.u32.u64 %0, t; }" : "=r"(a) : "l"(p));
    return a;
}
#define CP16(saddr, gptr) \
    asm volatile("cp.async.cg.shared.global [%0], [%1], 16;" :: "r"(saddr), "l"(gptr) : "memory")
#define CP_COMMIT() asm volatile("cp.async.commit_group;" ::: "memory")
#define CP_WAIT1()  asm volatile("cp.async.wait_group 1;" ::: "memory")
#define CP_WAIT0()  asm volatile("cp.async.wait_group 0;" ::: "memory")
#define LDSM4(r0, r1, r2, r3, addr) \
    asm volatile("ldmatrix.sync.aligned.m8n8.x4.shared.b16 {%0,%1,%2,%3}, [%4];" \
        : "=r"(r0), "=r"(r1), "=r"(r2), "=r"(r3) : "r"(addr))
#define MMA16816(c, a, b0v, b1v) \
    asm volatile("mma.sync.aligned.m16n8k16.row.col.f32.bf16.bf16.f32 " \
        "{%0,%1,%2,%3}, {%4,%5,%6,%7}, {%8,%9}, {%0,%1,%2,%3};" \
        : "+f"((c)[0]), "+f"((c)[1]), "+f"((c)[2]), "+f"((c)[3]) \
        : "r"((a)[0]), "r"((a)[1]), "r"((a)[2]), "r"((a)[3]), "r"(b0v), "r"(b1v))

// ================= HMMA split-bf16 GEMM =================
// C[M,N] = A[M,K] @ W[N,K]^T (+bias), A/W given as bf16 hi/lo pairs, K-major.
// CTA tile 128x128x64; 8 warps (2m x 4n), warp tile 64x32.
#define GM_BM 128
#define GM_BN 128
#define GM_BK 64
#define GM_OFF_AH 0
#define GM_OFF_AL (16 * 1024)
#define GM_OFF_BH (32 * 1024)
#define GM_OFF_BL (48 * 1024)
#define GM_STAGE  (64 * 1024)
#define GM_SMEM   (2 * GM_STAGE)

template<bool HAS_BIAS>
__global__ __launch_bounds__(256) void gemm_mma(
    const __nv_bfloat16* __restrict__ Ah, const __nv_bfloat16* __restrict__ Al,
    const __nv_bfloat16* __restrict__ Wh, const __nv_bfloat16* __restrict__ Wl,
    const float* __restrict__ bias, float* __restrict__ C,
    int K, int ldc)
{
    extern __shared__ char smem[];
    const uint32_t sbase = smem_u32(smem);
    const int tid = threadIdx.x;
    const int wid = tid >> 5, lane = tid & 31;
    const int warp_m = wid >> 2, warp_n = wid & 3;
    const int bm = blockIdx.x, bn = blockIdx.y;

    const __nv_bfloat16* baseAh = Ah + (size_t)bm * GM_BM * K;
    const __nv_bfloat16* baseAl = Al + (size_t)bm * GM_BM * K;
    const __nv_bfloat16* baseBh = Wh + (size_t)bn * GM_BN * K;
    const __nv_bfloat16* baseBl = Wl + (size_t)bn * GM_BN * K;

    // loader thread mapping: 4 passes x (32 rows x 8 units of 16B)
    const int lrow0 = tid >> 3;
    const int lunit = tid & 7;

#define LOAD_STAGE(st, k0elem) do { \
        const uint32_t _sb = sbase + (st) * GM_STAGE; \
        _Pragma("unroll") \
        for (int _p = 0; _p < 4; _p++) { \
            const int _r = _p * 32 + lrow0; \
            const uint32_t _soff = (uint32_t)_r * 128u + \
                (((uint32_t)lunit * 16u) ^ (uint32_t)((_r & 7) << 4)); \
            const size_t _eo = (size_t)_r * K + (k0elem) + lunit * 8; \
            CP16(_sb + GM_OFF_AH + _soff, baseAh + _eo); \
            CP16(_sb + GM_OFF_AL + _soff, baseAl + _eo); \
            CP16(_sb + GM_OFF_BH + _soff, baseBh + _eo); \
            CP16(_sb + GM_OFF_BL + _soff, baseBl + _eo); \
        } \
        CP_COMMIT(); \
    } while (0)

    // per-lane ldmatrix row offsets
    const int lr = lane & 15;            // row within 16-row block
    const uint32_t kb_lane = (uint32_t)(lane >> 4) * 16u;  // +8 k (=16B) for upper half
    uint32_t a_ro[4], a_xm[4];
#pragma unroll
    for (int mb = 0; mb < 4; mb++) {
        const int r = warp_m * 64 + mb * 16 + lr;
        a_ro[mb] = (uint32_t)r * 128u;
        a_xm[mb] = (uint32_t)((r & 7) << 4);
    }
    uint32_t b_ro[2], b_xm[2];
#pragma unroll
    for (int g = 0; g < 2; g++) {
        const int r = warp_n * 32 + g * 16 + lr;
        b_ro[g] = (uint32_t)r * 128u;
        b_xm[g] = (uint32_t)((r & 7) << 4);
    }

    float acc[4][4][4] = {};

    const int NC = K / GM_BK;
    LOAD_STAGE(0, 0);

    for (int i = 0; i < NC; i++) {
        if (i + 1 < NC) { LOAD_STAGE((i + 1) & 1, (i + 1) * GM_BK); CP_WAIT1(); }
        else            { CP_WAIT0(); }
        __syncthreads();

        const uint32_t sb = sbase + (i & 1) * GM_STAGE;
#pragma unroll
        for (int ks = 0; ks < 4; ks++) {
            const uint32_t kb = (uint32_t)ks * 32u + kb_lane;
            uint32_t ah[4][4], al[4][4];
#pragma unroll
            for (int mb = 0; mb < 4; mb++) {
                const uint32_t offh = sb + GM_OFF_AH + a_ro[mb] + (kb ^ a_xm[mb]);
                LDSM4(ah[mb][0], ah[mb][1], ah[mb][2], ah[mb][3], offh);
                const uint32_t offl = sb + GM_OFF_AL + a_ro[mb] + (kb ^ a_xm[mb]);
                LDSM4(al[mb][0], al[mb][1], al[mb][2], al[mb][3], offl);
            }
            uint32_t bh[2][4], bl[2][4];
#pragma unroll
            for (int g = 0; g < 2; g++) {
                const uint32_t offh = sb + GM_OFF_BH + b_ro[g] + (kb ^ b_xm[g]);
                LDSM4(bh[g][0], bh[g][1], bh[g][2], bh[g][3], offh);
                const uint32_t offl = sb + GM_OFF_BL + b_ro[g] + (kb ^ b_xm[g]);
                LDSM4(bl[g][0], bl[g][1], bl[g][2], bl[g][3], offl);
            }
#pragma unroll
            for (int mb = 0; mb < 4; mb++) {
#pragma unroll
                for (int nf = 0; nf < 4; nf++) {
                    const int g = nf >> 1, j = nf & 1;
                    MMA16816(acc[mb][nf], ah[mb], bh[g][j], bh[g][2 + j]);
                    MMA16816(acc[mb][nf], ah[mb], bl[g][j], bl[g][2 + j]);
                    MMA16816(acc[mb][nf], al[mb], bh[g][j], bh[g][2 + j]);
                }
            }
        }
        __syncthreads();
    }

    // epilogue: fragment -> gmem (float2 per fragment half)
    const int qrow = lane >> 2;
    const int qcol = (lane & 3) * 2;
#pragma unroll
    for (int mb = 0; mb < 4; mb++) {
        const int m0 = bm * GM_BM + warp_m * 64 + mb * 16 + qrow;
#pragma unroll
        for (int nf = 0; nf < 4; nf++) {
            const int n0 = bn * GM_BN + warp_n * 32 + nf * 8 + qcol;
            float b0 = 0.f, b1 = 0.f;
            if (HAS_BIAS) { b0 = bias[n0]; b1 = bias[n0 + 1]; }
            float2 v0, v1;
            v0.x = acc[mb][nf][0] + b0; v0.y = acc[mb][nf][1] + b1;
            v1.x = acc[mb][nf][2] + b0; v1.y = acc[mb][nf][3] + b1;
            *(float2*)(C + (size_t)m0 * ldc + n0)       = v0;
            *(float2*)(C + (size_t)(m0 + 8) * ldc + n0) = v1;
        }
    }
#undef LOAD_STAGE
}

// ================= LayerNorm -> split bf16 =================
__global__ __launch_bounds__(256) void ln_split_kernel(
    const float* __restrict__ x, const float* __restrict__ w,
    const float* __restrict__ bvec,
    __nv_bfloat16* __restrict__ oh, __nv_bfloat16* __restrict__ ol)
{
    int row = blockIdx.x;
    int tid = threadIdx.x;
    const float* xr = x + (size_t)row * HID;
    float4 v[4];
    float sum = 0.f, ss = 0.f;
#pragma unroll
    for (int i = 0; i < 4; i++) {
        v[i] = *(const float4*)(xr + (i * 256 + tid) * 4);
        sum += v[i].x + v[i].y + v[i].z + v[i].w;
        ss  += v[i].x * v[i].x + v[i].y * v[i].y + v[i].z * v[i].z + v[i].w * v[i].w;
    }
#pragma unroll
    for (int off = 16; off > 0; off >>= 1) {
        sum += __shfl_xor_sync(0xffffffffu, sum, off);
        ss  += __shfl_xor_sync(0xffffffffu, ss,  off);
    }
    __shared__ float r0[8], r1[8];
    __shared__ float s_mu, s_rstd;
    int wid = tid >> 5, lane = tid & 31;
    if (lane == 0) { r0[wid] = sum; r1[wid] = ss; }
    __syncthreads();
    if (tid == 0) {
        float s = 0.f, q = 0.f;
        for (int i = 0; i < 8; i++) { s += r0[i]; q += r1[i]; }
        float mu  = s * (1.f / HID);
        float var = q * (1.f / HID) - mu * mu;
        s_mu = mu; s_rstd = rsqrtf(var + 1e-5f);
    }
    __syncthreads();
    float mu = s_mu, rstd = s_rstd;
#pragma unroll
    for (int i = 0; i < 4; i++) {
        int c = (i * 256 + tid) * 4;
        float4 wv = *(const float4*)(w + c);
        float4 bv = *(const float4*)(bvec + c);
        float o[4];
        o[0] = (v[i].x - mu) * rstd * wv.x + bv.x;
        o[1] = (v[i].y - mu) * rstd * wv.y + bv.y;
        o[2] = (v[i].z - mu) * rstd * wv.z + bv.z;
        o[3] = (v[i].w - mu) * rstd * wv.w + bv.w;
        __nv_bfloat16 h[4], l[4];
#pragma unroll
        for (int j = 0; j < 4; j++) {
            h[j] = __float2bfloat16(o[j]);
            l[j] = __float2bfloat16(o[j] - __bfloat162float(h[j]));
        }
        *(uint2*)(oh + (size_t)row * HID + c) = *(uint2*)h;
        *(uint2*)(ol + (size_t)row * HID + c) = *(uint2*)l;
    }
}

// ================= transpose + split: in[K,N] f32 -> out[N,K] bf16 hi/lo =================
__global__ __launch_bounds__(256) void transpose_split_kernel(
    const float* __restrict__ in, __nv_bfloat16* __restrict__ oh,
    __nv_bfloat16* __restrict__ ol, int Kdim, int Ndim)
{
    __shared__ float tile[32][33];
    int n0 = blockIdx.x * 32, k0 = blockIdx.y * 32;
    int tx = threadIdx.x, ty = threadIdx.y;   // block (32,8)
#pragma unroll
    for (int i = 0; i < 32; i += 8)
        tile[ty + i][tx] = in[(size_t)(k0 + ty + i) * Ndim + n0 + tx];
    __syncthreads();
#pragma unroll
    for (int i = 0; i < 32; i += 8) {
        float v = tile[tx][ty + i];
        __nv_bfloat16 h = __float2bfloat16(v);
        size_t idx = (size_t)(n0 + ty + i) * Kdim + k0 + tx;
        oh[idx] = h;
        ol[idx] = __float2bfloat16(v - __bfloat162float(h));
    }
}

// ================= split f32 -> bf16 hi/lo (elementwise) =================
__global__ __launch_bounds__(256) void split_kernel(
    const float* __restrict__ in, __nv_bfloat16* __restrict__ oh,
    __nv_bfloat16* __restrict__ ol, size_t n)
{
    size_t i = (size_t)blockIdx.x * 1024 + threadIdx.x * 4;
    if (i >= n) return;
    float4 v = *(const float4*)(in + i);
    float o[4] = {v.x, v.y, v.z, v.w};
    __nv_bfloat16 h[4], l[4];
#pragma unroll
    for (int j = 0; j < 4; j++) {
        h[j] = __float2bfloat16(o[j]);
        l[j] = __float2bfloat16(o[j] - __bfloat162float(h[j]));
    }
    *(uint2*)(oh + i) = *(uint2*)h;
    *(uint2*)(ol + i) = *(uint2*)l;
}

// ================= SIMT SGEMM (QK^T / PV) =================
#define BM 128
#define BN 128
#define BK 8
#define TM 8
#define TN 8

template<bool TRANS_B, bool CAUSAL>
__global__ __launch_bounds__(256) void sgemm_k(
    const float* __restrict__ Ab, const float* __restrict__ Bb,
    float* __restrict__ Cb,
    int K, int lda, int ldb, int ldc,
    long long sA1, long long sA2,
    long long sB1, long long sB2,
    long long sC1, long long sC2,
    float alpha)
{
    int bn = blockIdx.x, bm = blockIdx.y;
    if (CAUSAL && bn > bm) return;
    int z = blockIdx.z;
    const float* A = Ab + (long long)(z >> 5) * sA1 + (long long)(z & 31) * sA2;
    const float* B = Bb + (long long)(z >> 5) * sB1 + (long long)(z & 31) * sB2;
    float*       C = Cb + (long long)(z >> 5) * sC1 + (long long)(z & 31) * sC2;

    __shared__ float As[BK][BM];
    __shared__ float Bs[BK][BN];

    int tid = threadIdx.x;
    int tx = tid & 15;
    int ty = tid >> 4;

    int arow = tid >> 1;
    int acol = (tid & 1) * 4;
    const float* Aptr = A + (long long)(bm * BM + arow) * lda + acol;

    const float* Bptr;
    int brow = 0, bcol = 0;
    if (TRANS_B) {
        Bptr = B + (long long)(bn * BN + arow) * ldb + acol;
    } else {
        brow = tid >> 5;
        bcol = (tid & 31) * 4;
        Bptr = B + (long long)brow * ldb + bn * BN + bcol;
    }

    float acc[TM][TN] = {};

    for (int k0 = 0; k0 < K; k0 += BK) {
        float4 av = *(const float4*)(Aptr);
        Aptr += BK;
        As[acol + 0][arow] = av.x;
        As[acol + 1][arow] = av.y;
        As[acol + 2][arow] = av.z;
        As[acol + 3][arow] = av.w;
        if (TRANS_B) {
            float4 bv = *(const float4*)(Bptr);
            Bptr += BK;
            Bs[acol + 0][arow] = bv.x;
            Bs[acol + 1][arow] = bv.y;
            Bs[acol + 2][arow] = bv.z;
            Bs[acol + 3][arow] = bv.w;
        } else {
            float4 bv = *(const float4*)(Bptr);
            Bptr += (long long)BK * ldb;
            *(float4*)&Bs[brow][bcol] = bv;
        }
        __syncthreads();

#pragma unroll
        for (int kk = 0; kk < BK; kk++) {
            float4 a0 = *(const float4*)&As[kk][ty * TM];
            float4 a1 = *(const float4*)&As[kk][ty * TM + 4];
            float4 b0 = *(const float4*)&Bs[kk][tx * TN];
            float4 b1 = *(const float4*)&Bs[kk][tx * TN + 4];
            float af[TM] = {a0.x, a0.y, a0.z, a0.w, a1.x, a1.y, a1.z, a1.w};
            float bf[TN] = {b0.x, b0.y, b0.z, b0.w, b1.x, b1.y, b1.z, b1.w};
#pragma unroll
            for (int i = 0; i < TM; i++)
#pragma unroll
                for (int j = 0; j < TN; j++)
                    acc[i][j] += af[i] * bf[j];
        }
        __syncthreads();
    }

#pragma unroll
    for (int i = 0; i < TM; i++) {
        long long crow = (long long)(bm * BM + ty * TM + i) * ldc;
#pragma unroll
        for (int j = 0; j < TN; j += 4) {
            int col = bn * BN + tx * TN + j;
            float4 o;
            o.x = acc[i][j + 0] * alpha;
            o.y = acc[i][j + 1] * alpha;
            o.z = acc[i][j + 2] * alpha;
            o.w = acc[i][j + 3] * alpha;
            *(float4*)(C + crow + col) = o;
        }
    }
}

// ================= causal softmax =================
__global__ __launch_bounds__(256) void softmax_kernel(
    float* __restrict__ scores, const float* __restrict__ mask)
{
    int q = blockIdx.x, h = blockIdx.y, b = blockIdx.z;
    float* row = scores + (((long long)(b * NHEADS + h) * SEQ + q) * SEQ);
    int tid = threadIdx.x;
    int c0 = tid * 4;

    float4 v  = *(const float4*)(row + c0);
    float4 mk = *(const float4*)(mask + b * SEQ + c0);
    float vals[4] = {v.x + mk.x, v.y + mk.y, v.z + mk.z, v.w + mk.w};
#pragma unroll
    for (int j = 0; j < 4; j++)
        if (c0 + j > q) vals[j] += -10000.0f;

    float m = fmaxf(fmaxf(vals[0], vals[1]), fmaxf(vals[2], vals[3]));
#pragma unroll
    for (int off = 16; off > 0; off >>= 1)
        m = fmaxf(m, __shfl_xor_sync(0xffffffffu, m, off));

    __shared__ float rmax[8], rsum[8];
    __shared__ float s_max, s_inv;
    int wid = tid >> 5, lane = tid & 31;
    if (lane == 0) rmax[wid] = m;
    __syncthreads();
    if (tid == 0) {
        float t = rmax[0];
        for (int i = 1; i < 8; i++) t = fmaxf(t, rmax[i]);
        s_max = t;
    }
    __syncthreads();
    float rowmax = s_max;

    float e[4], sum = 0.f;
#pragma unroll
    for (int j = 0; j < 4; j++) { e[j] = __expf(vals[j] - rowmax); sum += e[j]; }
#pragma unroll
    for (int off = 16; off > 0; off >>= 1)
        sum += __shfl_xor_sync(0xffffffffu, sum, off);
    if (lane == 0) rsum[wid] = sum;
    __syncthreads();
    if (tid == 0) {
        float t = 0.f;
        for (int i = 0; i < 8; i++) t += rsum[i];
        s_inv = 1.f / t;
    }
    __syncthreads();
    float inv = s_inv;

    float4 o;
    o.x = e[0] * inv; o.y = e[1] * inv; o.z = e[2] * inv; o.w = e[3] * inv;
    *(float4*)(row + c0) = o;
}

// ================= launch =================
extern "C" void kernel_launch(void* const* d_in, const int* in_sizes, int n_in,
                              void* d_out, int out_size)
{
    const float* x       = (const float*)d_in[0];
    const float* mask    = (const float*)d_in[1];
    const float* norm_w  = (const float*)d_in[2];
    const float* norm_b  = (const float*)d_in[3];
    const float* qkv_w   = (const float*)d_in[4];
    const float* qkv_b   = (const float*)d_in[5];
    const float* attn_ow = (const float*)d_in[6];
    float* out = (float*)d_out;

    __nv_bfloat16 *p_ah, *p_al, *p_wqh, *p_wql, *p_woh, *p_wol, *p_ch, *p_cl;
    float *p_qkv, *p_scores, *p_ctx;
    cudaGetSymbolAddress((void**)&p_ah,  g_a_hi);
    cudaGetSymbolAddress((void**)&p_al,  g_a_lo);
    cudaGetSymbolAddress((void**)&p_wqh, g_wq_hi);
    cudaGetSymbolAddress((void**)&p_wql, g_wq_lo);
    cudaGetSymbolAddress((void**)&p_woh, g_wo_hi);
    cudaGetSymbolAddress((void**)&p_wol, g_wo_lo);
    cudaGetSymbolAddress((void**)&p_ch,  g_c_hi);
    cudaGetSymbolAddress((void**)&p_cl,  g_c_lo);
    cudaGetSymbolAddress((void**)&p_qkv,    g_qkv);
    cudaGetSymbolAddress((void**)&p_scores, g_scores);
    cudaGetSymbolAddress((void**)&p_ctx,    g_ctx);

    cudaFuncSetAttribute(gemm_mma<true>,  cudaFuncAttributeMaxDynamicSharedMemorySize, GM_SMEM);
    cudaFuncSetAttribute(gemm_mma<false>, cudaFuncAttributeMaxDynamicSharedMemorySize, GM_SMEM);

    const float inv_sqrt_hd = 0.08838834764831845f;  // 1/sqrt(128)

    // 1) LayerNorm -> split bf16 activations
    ln_split_kernel<<<TOKENS, 256>>>(x, norm_w, norm_b, p_ah, p_al);

    // 2) weight transpose+split to [N,K] bf16 hi/lo
    transpose_split_kernel<<<dim3(H3 / 32, HID / 32), dim3(32, 8)>>>(qkv_w, p_wqh, p_wql, HID, H3);
    transpose_split_kernel<<<dim3(HID / 32, HID / 32), dim3(32, 8)>>>(attn_ow, p_woh, p_wol, HID, HID);

    // 3) QKV GEMM (HMMA): [2048,4096] @ [4096,12288] + bias
    gemm_mma<true><<<dim3(TOKENS / GM_BM, H3 / GM_BN), 256, GM_SMEM>>>(
        p_ah, p_al, p_wqh, p_wql, qkv_b, p_qkv, HID, H3);

    // 4) scores = Q @ K^T * 1/sqrt(hd)  (SIMT, causal block skip)
    sgemm_k<true, true><<<dim3(SEQ / BN, SEQ / BM, BATCH * NHEADS), 256>>>(
        p_qkv, p_qkv + HID, p_scores,
        HDIM, H3, H3, SEQ,
        (long long)SEQ * H3, HDIM,
        (long long)SEQ * H3, HDIM,
        (long long)NHEADS * SEQ * SEQ, (long long)SEQ * SEQ,
        inv_sqrt_hd);

    // 5) softmax
    softmax_kernel<<<dim3(SEQ, NHEADS, BATCH), 256>>>(p_scores, mask);

    // 6) ctx = P @ V (SIMT)
    sgemm_k<false, false><<<dim3(HDIM / BN, SEQ / BM, BATCH * NHEADS), 256>>>(
        p_scores, p_qkv + 2 * HID, p_ctx,
        SEQ, SEQ, H3, HID,
        (long long)NHEADS * SEQ * SEQ, (long long)SEQ * SEQ,
        (long long)SEQ * H3, HDIM,
        (long long)SEQ * HID, HDIM,
        1.0f);

    // 7) split ctx -> bf16 hi/lo
    split_kernel<<<(TOKENS * HID + 1023) / 1024, 256>>>(p_ctx, p_ch, p_cl, (size_t)TOKENS * HID);

    // 8) out = ctx @ attn_ow (HMMA)
    gemm_mma<false><<<dim3(TOKENS / GM_BM, HID / GM_BN), 256, GM_SMEM>>>(
        p_ch, p_cl, p_woh, p_wol, nullptr, out, HID, HID);
}

// round 6
// speedup vs baseline: 2.7783x; 1.1639x over previous
#include <cuda_runtime.h>
#include <cuda_bf16.h>
#include <cstdint>
#include <math.h>

#define HID    4096
#define NHEADS 32
#define HDIM   128
#define BATCH  2
#define SEQ    1024
#define TOKENS 2048
#define H3     12288

// ================= scratch (device globals) =================
__device__ __align__(16) __nv_bfloat16 g_a_hi[(size_t)TOKENS * HID];
__device__ __align__(16) __nv_bfloat16 g_a_lo[(size_t)TOKENS * HID];
__device__ __align__(16) __nv_bfloat16 g_wq_hi[(size_t)H3 * HID];     // qkv_w^T [N,K]
__device__ __align__(16) __nv_bfloat16 g_wq_lo[(size_t)H3 * HID];
__device__ __align__(16) __nv_bfloat16 g_wo_hi[(size_t)HID * HID];    // attn_ow^T [N,K]
__device__ __align__(16) __nv_bfloat16 g_wo_lo[(size_t)HID * HID];
__device__ __align__(16) __nv_bfloat16 g_qkv_hi[(size_t)TOKENS * H3];
__device__ __align__(16) __nv_bfloat16 g_qkv_lo[(size_t)TOKENS * H3];
__device__ __align__(16) __nv_bfloat16 g_vT_hi[(size_t)BATCH * NHEADS * HDIM * SEQ];
__device__ __align__(16) __nv_bfloat16 g_vT_lo[(size_t)BATCH * NHEADS * HDIM * SEQ];
__device__ __align__(16) float g_scores[(size_t)BATCH * NHEADS * SEQ * SEQ];
__device__ __align__(16) __nv_bfloat16 g_p_hi[(size_t)BATCH * NHEADS * SEQ * SEQ];
__device__ __align__(16) __nv_bfloat16 g_p_lo[(size_t)BATCH * NHEADS * SEQ * SEQ];
__device__ __align__(16) __nv_bfloat16 g_c_hi[(size_t)TOKENS * HID];
__device__ __align__(16) __nv_bfloat16 g_c_lo[(size_t)TOKENS * HID];

// ================= helpers =================
__device__ __forceinline__ uint32_t smem_u32(const void* p) {
    uint32_t a;
    asm("{ .reg .u64 t; cvta.to.shared.u64 t, %1; cvt.u32.u64 %0, t; }" : "=r"(a) : "l"(p));
    return a;
}
#define CP16(saddr, gptr) \
    asm volatile("cp.async.cg.shared.global [%0], [%1], 16;" :: "r"(saddr), "l"(gptr) : "memory")
#define CP_COMMIT() asm volatile("cp.async.commit_group;" ::: "memory")
#define CP_WAIT1()  asm volatile("cp.async.wait_group 1;" ::: "memory")
#define CP_WAIT0()  asm volatile("cp.async.wait_group 0;" ::: "memory")
#define LDSM4(r0, r1, r2, r3, addr) \
    asm volatile("ldmatrix.sync.aligned.m8n8.x4.shared.b16 {%0,%1,%2,%3}, [%4];" \
        : "=r"(r0), "=r"(r1), "=r"(r2), "=r"(r3) : "r"(addr))
#define MMA16816(c, a, b0v, b1v) \
    asm volatile("mma.sync.aligned.m16n8k16.row.col.f32.bf16.bf16.f32 " \
        "{%0,%1,%2,%3}, {%4,%5,%6,%7}, {%8,%9}, {%0,%1,%2,%3};" \
        : "+f"((c)[0]), "+f"((c)[1]), "+f"((c)[2]), "+f"((c)[3]) \
        : "r"((a)[0]), "r"((a)[1]), "r"((a)[2]), "r"((a)[3]), "r"(b0v), "r"(b1v))

// ================= HMMA split-bf16 GEMM (generalized) =================
// C[M,N] = alpha * A[M,K] @ W[N,K]^T (+bias), A/W bf16 hi/lo, row strides lda/ldb.
// Batched via blockIdx.z: off = (z>>5)*s?1 + (z&31)*s?2.
// CAUSAL: skip tile if bn > bm.  KLIM: K limited to (bm+1)*128 (causal PV).
// SPLIT_OUT: write bf16 hi/lo instead of fp32.
#define GM_BM 128
#define GM_BN 128
#define GM_BK 64
#define GM_OFF_AH 0
#define GM_OFF_AL (16 * 1024)
#define GM_OFF_BH (32 * 1024)
#define GM_OFF_BL (48 * 1024)
#define GM_STAGE  (64 * 1024)
#define GM_SMEM   (2 * GM_STAGE)

template<bool HAS_BIAS, bool SPLIT_OUT, bool CAUSAL, bool KLIM>
__global__ __launch_bounds__(256) void gemm_mma(
    const __nv_bfloat16* __restrict__ Ah, const __nv_bfloat16* __restrict__ Al,
    const __nv_bfloat16* __restrict__ Wh, const __nv_bfloat16* __restrict__ Wl,
    const float* __restrict__ bias,
    float* __restrict__ Cf,
    __nv_bfloat16* __restrict__ Ch, __nv_bfloat16* __restrict__ Cl,
    int K, int lda, int ldb, int ldc,
    long long sA1, long long sA2, long long sB1, long long sB2,
    long long sC1, long long sC2, float alpha)
{
    extern __shared__ char smem[];
    const int bm = blockIdx.x, bn = blockIdx.y;
    if (CAUSAL && bn > bm) return;

    const uint32_t sbase = smem_u32(smem);
    const int tid = threadIdx.x;
    const int wid = tid >> 5, lane = tid & 31;
    const int warp_m = wid >> 2, warp_n = wid & 3;

    const int z = blockIdx.z;
    const long long offA = (long long)(z >> 5) * sA1 + (long long)(z & 31) * sA2;
    const long long offB = (long long)(z >> 5) * sB1 + (long long)(z & 31) * sB2;
    const long long offC = (long long)(z >> 5) * sC1 + (long long)(z & 31) * sC2;

    const __nv_bfloat16* baseAh = Ah + offA + (size_t)bm * GM_BM * lda;
    const __nv_bfloat16* baseAl = Al + offA + (size_t)bm * GM_BM * lda;
    const __nv_bfloat16* baseBh = Wh + offB + (size_t)bn * GM_BN * ldb;
    const __nv_bfloat16* baseBl = Wl + offB + (size_t)bn * GM_BN * ldb;

    // loader thread mapping: 4 passes x (32 rows x 8 units of 16B)
    const int lrow0 = tid >> 3;
    const int lunit = tid & 7;

#define LOAD_STAGE(st, k0elem) do { \
        const uint32_t _sb = sbase + (st) * GM_STAGE; \
        _Pragma("unroll") \
        for (int _p = 0; _p < 4; _p++) { \
            const int _r = _p * 32 + lrow0; \
            const uint32_t _soff = (uint32_t)_r * 128u + \
                (((uint32_t)lunit * 16u) ^ (uint32_t)((_r & 7) << 4)); \
            const size_t _eoA = (size_t)_r * lda + (k0elem) + lunit * 8; \
            const size_t _eoB = (size_t)_r * ldb + (k0elem) + lunit * 8; \
            CP16(_sb + GM_OFF_AH + _soff, baseAh + _eoA); \
            CP16(_sb + GM_OFF_AL + _soff, baseAl + _eoA); \
            CP16(_sb + GM_OFF_BH + _soff, baseBh + _eoB); \
            CP16(_sb + GM_OFF_BL + _soff, baseBl + _eoB); \
        } \
        CP_COMMIT(); \
    } while (0)

    // per-lane ldmatrix row offsets
    const int lr = lane & 15;
    const uint32_t kb_lane = (uint32_t)(lane >> 4) * 16u;
    uint32_t a_ro[4], a_xm[4];
#pragma unroll
    for (int mb = 0; mb < 4; mb++) {
        const int r = warp_m * 64 + mb * 16 + lr;
        a_ro[mb] = (uint32_t)r * 128u;
        a_xm[mb] = (uint32_t)((r & 7) << 4);
    }
    uint32_t b_ro[2], b_xm[2];
#pragma unroll
    for (int g = 0; g < 2; g++) {
        const int r = warp_n * 32 + g * 16 + lr;
        b_ro[g] = (uint32_t)r * 128u;
        b_xm[g] = (uint32_t)((r & 7) << 4);
    }

    float acc[4][4][4] = {};

    int Keff = K;
    if (KLIM) { int kl = (bm + 1) * GM_BM; Keff = kl < K ? kl : K; }
    const int NC = Keff / GM_BK;
    LOAD_STAGE(0, 0);

    for (int i = 0; i < NC; i++) {
        if (i + 1 < NC) { LOAD_STAGE((i + 1) & 1, (size_t)(i + 1) * GM_BK); CP_WAIT1(); }
        else            { CP_WAIT0(); }
        __syncthreads();

        const uint32_t sb = sbase + (i & 1) * GM_STAGE;
#pragma unroll
        for (int ks = 0; ks < 4; ks++) {
            const uint32_t kb = (uint32_t)ks * 32u + kb_lane;
            uint32_t ah[4][4], al[4][4];
#pragma unroll
            for (int mb = 0; mb < 4; mb++) {
                const uint32_t offh = sb + GM_OFF_AH + a_ro[mb] + (kb ^ a_xm[mb]);
                LDSM4(ah[mb][0], ah[mb][1], ah[mb][2], ah[mb][3], offh);
                const uint32_t offl = sb + GM_OFF_AL + a_ro[mb] + (kb ^ a_xm[mb]);
                LDSM4(al[mb][0], al[mb][1], al[mb][2], al[mb][3], offl);
            }
            uint32_t bh[2][4], bl[2][4];
#pragma unroll
            for (int g = 0; g < 2; g++) {
                const uint32_t offh = sb + GM_OFF_BH + b_ro[g] + (kb ^ b_xm[g]);
                LDSM4(bh[g][0], bh[g][1], bh[g][2], bh[g][3], offh);
                const uint32_t offl = sb + GM_OFF_BL + b_ro[g] + (kb ^ b_xm[g]);
                LDSM4(bl[g][0], bl[g][1], bl[g][2], bl[g][3], offl);
            }
#pragma unroll
            for (int mb = 0; mb < 4; mb++) {
#pragma unroll
                for (int nf = 0; nf < 4; nf++) {
                    const int g = nf >> 1, j = nf & 1;
                    MMA16816(acc[mb][nf], ah[mb], bh[g][j], bh[g][2 + j]);
                    MMA16816(acc[mb][nf], ah[mb], bl[g][j], bl[g][2 + j]);
                    MMA16816(acc[mb][nf], al[mb], bh[g][j], bh[g][2 + j]);
                }
            }
        }
        __syncthreads();
    }

    // epilogue
    const int qrow = lane >> 2;
    const int qcol = (lane & 3) * 2;
#pragma unroll
    for (int mb = 0; mb < 4; mb++) {
        const int m0 = bm * GM_BM + warp_m * 64 + mb * 16 + qrow;
#pragma unroll
        for (int nf = 0; nf < 4; nf++) {
            const int n0 = bn * GM_BN + warp_n * 32 + nf * 8 + qcol;
            float b0 = 0.f, b1 = 0.f;
            if (HAS_BIAS) { b0 = bias[n0]; b1 = bias[n0 + 1]; }
            float v00 = acc[mb][nf][0] * alpha + b0;
            float v01 = acc[mb][nf][1] * alpha + b1;
            float v10 = acc[mb][nf][2] * alpha + b0;
            float v11 = acc[mb][nf][3] * alpha + b1;
            if (SPLIT_OUT) {
                __nv_bfloat162 h0, l0, h1, l1;
                h0.x = __float2bfloat16(v00);
                h0.y = __float2bfloat16(v01);
                l0.x = __float2bfloat16(v00 - __bfloat162float(h0.x));
                l0.y = __float2bfloat16(v01 - __bfloat162float(h0.y));
                h1.x = __float2bfloat16(v10);
                h1.y = __float2bfloat16(v11);
                l1.x = __float2bfloat16(v10 - __bfloat162float(h1.x));
                l1.y = __float2bfloat16(v11 - __bfloat162float(h1.y));
                *(__nv_bfloat162*)(Ch + offC + (size_t)m0 * ldc + n0)       = h0;
                *(__nv_bfloat162*)(Cl + offC + (size_t)m0 * ldc + n0)       = l0;
                *(__nv_bfloat162*)(Ch + offC + (size_t)(m0 + 8) * ldc + n0) = h1;
                *(__nv_bfloat162*)(Cl + offC + (size_t)(m0 + 8) * ldc + n0) = l1;
            } else {
                float2 r0, r1;
                r0.x = v00; r0.y = v01;
                r1.x = v10; r1.y = v11;
                *(float2*)(Cf + offC + (size_t)m0 * ldc + n0)       = r0;
                *(float2*)(Cf + offC + (size_t)(m0 + 8) * ldc + n0) = r1;
            }
        }
    }
#undef LOAD_STAGE
}

// ================= LayerNorm -> split bf16 =================
__global__ __launch_bounds__(256) void ln_split_kernel(
    const float* __restrict__ x, const float* __restrict__ w,
    const float* __restrict__ bvec,
    __nv_bfloat16* __restrict__ oh, __nv_bfloat16* __restrict__ ol)
{
    int row = blockIdx.x;
    int tid = threadIdx.x;
    const float* xr = x + (size_t)row * HID;
    float4 v[4];
    float sum = 0.f, ss = 0.f;
#pragma unroll
    for (int i = 0; i < 4; i++) {
        v[i] = *(const float4*)(xr + (i * 256 + tid) * 4);
        sum += v[i].x + v[i].y + v[i].z + v[i].w;
        ss  += v[i].x * v[i].x + v[i].y * v[i].y + v[i].z * v[i].z + v[i].w * v[i].w;
    }
#pragma unroll
    for (int off = 16; off > 0; off >>= 1) {
        sum += __shfl_xor_sync(0xffffffffu, sum, off);
        ss  += __shfl_xor_sync(0xffffffffu, ss,  off);
    }
    __shared__ float r0[8], r1[8];
    __shared__ float s_mu, s_rstd;
    int wid = tid >> 5, lane = tid & 31;
    if (lane == 0) { r0[wid] = sum; r1[wid] = ss; }
    __syncthreads();
    if (tid == 0) {
        float s = 0.f, q = 0.f;
        for (int i = 0; i < 8; i++) { s += r0[i]; q += r1[i]; }
        float mu  = s * (1.f / HID);
        float var = q * (1.f / HID) - mu * mu;
        s_mu = mu; s_rstd = rsqrtf(var + 1e-5f);
    }
    __syncthreads();
    float mu = s_mu, rstd = s_rstd;
#pragma unroll
    for (int i = 0; i < 4; i++) {
        int c = (i * 256 + tid) * 4;
        float4 wv = *(const float4*)(w + c);
        float4 bv = *(const float4*)(bvec + c);
        float o[4];
        o[0] = (v[i].x - mu) * rstd * wv.x + bv.x;
        o[1] = (v[i].y - mu) * rstd * wv.y + bv.y;
        o[2] = (v[i].z - mu) * rstd * wv.z + bv.z;
        o[3] = (v[i].w - mu) * rstd * wv.w + bv.w;
        __nv_bfloat16 h[4], l[4];
#pragma unroll
        for (int j = 0; j < 4; j++) {
            h[j] = __float2bfloat16(o[j]);
            l[j] = __float2bfloat16(o[j] - __bfloat162float(h[j]));
        }
        *(uint2*)(oh + (size_t)row * HID + c) = *(uint2*)h;
        *(uint2*)(ol + (size_t)row * HID + c) = *(uint2*)l;
    }
}

// ================= transpose + split: in[K,N] f32 -> out[N,K] bf16 hi/lo =================
__global__ __launch_bounds__(256) void transpose_split_kernel(
    const float* __restrict__ in, __nv_bfloat16* __restrict__ oh,
    __nv_bfloat16* __restrict__ ol, int Kdim, int Ndim)
{
    __shared__ float tile[32][33];
    int n0 = blockIdx.x * 32, k0 = blockIdx.y * 32;
    int tx = threadIdx.x, ty = threadIdx.y;   // block (32,8)
#pragma unroll
    for (int i = 0; i < 32; i += 8)
        tile[ty + i][tx] = in[(size_t)(k0 + ty + i) * Ndim + n0 + tx];
    __syncthreads();
#pragma unroll
    for (int i = 0; i < 32; i += 8) {
        float v = tile[tx][ty + i];
        __nv_bfloat16 h = __float2bfloat16(v);
        size_t idx = (size_t)(n0 + ty + i) * Kdim + k0 + tx;
        oh[idx] = h;
        ol[idx] = __float2bfloat16(v - __bfloat162float(h));
    }
}

// ================= batched bf16 transpose of V: [S,HD] (stride H3) -> [HD,S] =================
__global__ __launch_bounds__(256) void transpose_v_kernel(
    const __nv_bfloat16* __restrict__ qh, const __nv_bfloat16* __restrict__ ql,
    __nv_bfloat16* __restrict__ vth, __nv_bfloat16* __restrict__ vtl)
{
    __shared__ __nv_bfloat16 th[32][33];
    __shared__ __nv_bfloat16 tl[32][33];
    int z = blockIdx.z;
    int b = z >> 5, h = z & 31;
    const size_t in_off  = (size_t)b * SEQ * H3 + 2 * HID + (size_t)h * HDIM;
    const size_t out_off = (size_t)z * HDIM * SEQ;
    int k0 = blockIdx.x * 32;   // token dim
    int d0 = blockIdx.y * 32;   // head dim
    int tx = threadIdx.x, ty = threadIdx.y;  // (32, 8)
#pragma unroll
    for (int i = 0; i < 32; i += 8) {
        size_t src = in_off + (size_t)(k0 + ty + i) * H3 + d0 + tx;
        th[ty + i][tx] = qh[src];
        tl[ty + i][tx] = ql[src];
    }
    __syncthreads();
#pragma unroll
    for (int i = 0; i < 32; i += 8) {
        size_t dst = out_off + (size_t)(d0 + ty + i) * SEQ + k0 + tx;
        vth[dst] = th[tx][ty + i];
        vtl[dst] = tl[tx][ty + i];
    }
}

// ================= causal softmax: fp32 scores -> split bf16 P =================
__global__ __launch_bounds__(256) void softmax_kernel(
    const float* __restrict__ scores, const float* __restrict__ mask,
    __nv_bfloat16* __restrict__ ph, __nv_bfloat16* __restrict__ pl)
{
    int q = blockIdx.x, h = blockIdx.y, b = blockIdx.z;
    const size_t rowoff = (((size_t)(b * NHEADS + h) * SEQ + q) * SEQ);
    const float* row = scores + rowoff;
    int tid = threadIdx.x;
    int c0 = tid * 4;

    float4 v  = *(const float4*)(row + c0);
    float4 mk = *(const float4*)(mask + b * SEQ + c0);
    float vals[4] = {v.x + mk.x, v.y + mk.y, v.z + mk.z, v.w + mk.w};
#pragma unroll
    for (int j = 0; j < 4; j++)
        if (c0 + j > q) vals[j] += -10000.0f;

    float m = fmaxf(fmaxf(vals[0], vals[1]), fmaxf(vals[2], vals[3]));
#pragma unroll
    for (int off = 16; off > 0; off >>= 1)
        m = fmaxf(m, __shfl_xor_sync(0xffffffffu, m, off));

    __shared__ float rmax[8], rsum[8];
    __shared__ float s_max, s_inv;
    int wid = tid >> 5, lane = tid & 31;
    if (lane == 0) rmax[wid] = m;
    __syncthreads();
    if (tid == 0) {
        float t = rmax[0];
        for (int i = 1; i < 8; i++) t = fmaxf(t, rmax[i]);
        s_max = t;
    }
    __syncthreads();
    float rowmax = s_max;

    float e[4], sum = 0.f;
#pragma unroll
    for (int j = 0; j < 4; j++) { e[j] = __expf(vals[j] - rowmax); sum += e[j]; }
#pragma unroll
    for (int off = 16; off > 0; off >>= 1)
        sum += __shfl_xor_sync(0xffffffffu, sum, off);
    if (lane == 0) rsum[wid] = sum;
    __syncthreads();
    if (tid == 0) {
        float t = 0.f;
        for (int i = 0; i < 8; i++) t += rsum[i];
        s_inv = 1.f / t;
    }
    __syncthreads();
    float inv = s_inv;

    __nv_bfloat16 hh[4], ll[4];
#pragma unroll
    for (int j = 0; j < 4; j++) {
        float p = e[j] * inv;
        hh[j] = __float2bfloat16(p);
        ll[j] = __float2bfloat16(p - __bfloat162float(hh[j]));
    }
    *(uint2*)(ph + rowoff + c0) = *(uint2*)hh;
    *(uint2*)(pl + rowoff + c0) = *(uint2*)ll;
}

// ================= launch =================
extern "C" void kernel_launch(void* const* d_in, const int* in_sizes, int n_in,
                              void* d_out, int out_size)
{
    const float* x       = (const float*)d_in[0];
    const float* mask    = (const float*)d_in[1];
    const float* norm_w  = (const float*)d_in[2];
    const float* norm_b  = (const float*)d_in[3];
    const float* qkv_w   = (const float*)d_in[4];
    const float* qkv_b   = (const float*)d_in[5];
    const float* attn_ow = (const float*)d_in[6];
    float* out = (float*)d_out;

    __nv_bfloat16 *p_ah, *p_al, *p_wqh, *p_wql, *p_woh, *p_wol;
    __nv_bfloat16 *p_qh, *p_ql, *p_vth, *p_vtl, *p_ph, *p_pl, *p_ch, *p_cl;
    float *p_scores;
    cudaGetSymbolAddress((void**)&p_ah,  g_a_hi);
    cudaGetSymbolAddress((void**)&p_al,  g_a_lo);
    cudaGetSymbolAddress((void**)&p_wqh, g_wq_hi);
    cudaGetSymbolAddress((void**)&p_wql, g_wq_lo);
    cudaGetSymbolAddress((void**)&p_woh, g_wo_hi);
    cudaGetSymbolAddress((void**)&p_wol, g_wo_lo);
    cudaGetSymbolAddress((void**)&p_qh,  g_qkv_hi);
    cudaGetSymbolAddress((void**)&p_ql,  g_qkv_lo);
    cudaGetSymbolAddress((void**)&p_vth, g_vT_hi);
    cudaGetSymbolAddress((void**)&p_vtl, g_vT_lo);
    cudaGetSymbolAddress((void**)&p_ph,  g_p_hi);
    cudaGetSymbolAddress((void**)&p_pl,  g_p_lo);
    cudaGetSymbolAddress((void**)&p_ch,  g_c_hi);
    cudaGetSymbolAddress((void**)&p_cl,  g_c_lo);
    cudaGetSymbolAddress((void**)&p_scores, g_scores);

    cudaFuncSetAttribute((const void*)gemm_mma<true,  true,  false, false>, cudaFuncAttributeMaxDynamicSharedMemorySize, GM_SMEM);
    cudaFuncSetAttribute((const void*)gemm_mma<false, false, true,  false>, cudaFuncAttributeMaxDynamicSharedMemorySize, GM_SMEM);
    cudaFuncSetAttribute((const void*)gemm_mma<false, true,  false, true >, cudaFuncAttributeMaxDynamicSharedMemorySize, GM_SMEM);
    cudaFuncSetAttribute((const void*)gemm_mma<false, false, false, false>, cudaFuncAttributeMaxDynamicSharedMemorySize, GM_SMEM);

    const float inv_sqrt_hd = 0.08838834764831845f;  // 1/sqrt(128)

    // 1) LayerNorm -> split bf16 activations
    ln_split_kernel<<<TOKENS, 256>>>(x, norm_w, norm_b, p_ah, p_al);

    // 2) weight transpose+split to [N,K] bf16 hi/lo
    transpose_split_kernel<<<dim3(H3 / 32, HID / 32), dim3(32, 8)>>>(qkv_w, p_wqh, p_wql, HID, H3);
    transpose_split_kernel<<<dim3(HID / 32, HID / 32), dim3(32, 8)>>>(attn_ow, p_woh, p_wol, HID, HID);

    // 3) QKV GEMM + bias -> split bf16 qkv
    gemm_mma<true, true, false, false><<<dim3(TOKENS / GM_BM, H3 / GM_BN), 256, GM_SMEM>>>(
        p_ah, p_al, p_wqh, p_wql, qkv_b, nullptr, p_qh, p_ql,
        HID, HID, HID, H3,
        0, 0, 0, 0, 0, 0, 1.0f);

    // 4) transpose V -> vT [z][HD][S] (hi/lo separately, exact)
    transpose_v_kernel<<<dim3(SEQ / 32, HDIM / 32, BATCH * NHEADS), dim3(32, 8)>>>(
        p_qh, p_ql, p_vth, p_vtl);

    // 5) scores = Q @ K^T * 1/sqrt(hd), causal tile skip, fp32 out
    gemm_mma<false, false, true, false><<<dim3(SEQ / GM_BM, SEQ / GM_BN, BATCH * NHEADS), 256, GM_SMEM>>>(
        p_qh, p_ql, p_qh + HID, p_ql + HID, nullptr, p_scores, nullptr, nullptr,
        HDIM, H3, H3, SEQ,
        (long long)SEQ * H3, HDIM,
        (long long)SEQ * H3, HDIM,
        (long long)NHEADS * SEQ * SEQ, (long long)SEQ * SEQ,
        inv_sqrt_hd);

    // 6) softmax -> split bf16 P
    softmax_kernel<<<dim3(SEQ, NHEADS, BATCH), 256>>>(p_scores, mask, p_ph, p_pl);

    // 7) ctx = P @ V  (B = vT [HD,S]); causal K-limit; split bf16 out in [b,s,h*hd] layout
    gemm_mma<false, true, false, true><<<dim3(SEQ / GM_BM, HDIM / GM_BN, BATCH * NHEADS), 256, GM_SMEM>>>(
        p_ph, p_pl, p_vth, p_vtl, nullptr, nullptr, p_ch, p_cl,
        SEQ, SEQ, SEQ, HID,
        (long long)NHEADS * SEQ * SEQ, (long long)SEQ * SEQ,
        (long long)NHEADS * HDIM * SEQ, (long long)HDIM * SEQ,
        (long long)SEQ * HID, HDIM,
        1.0f);

    // 8) out = ctx @ attn_ow, fp32
    gemm_mma<false, false, false, false><<<dim3(TOKENS / GM_BM, HID / GM_BN), 256, GM_SMEM>>>(
        p_ch, p_cl, p_woh, p_wol, nullptr, out, nullptr, nullptr,
        HID, HID, HID, HID,
        0, 0, 0, 0, 0, 0, 1.0f);
}